// round 8
// baseline (speedup 1.0000x reference)
#include <cuda_runtime.h>
#include <stdint.h>

#define EPS 1e-10f
#define BLOCK 512

// Flag resolved on-device each launch: 1 if big0 is logits (has negatives),
// 0 if big0 is exp_noise (Exp(1), all nonnegative). Deterministic per replay.
__device__ int g_big0_is_logits;

__global__ void detect_kernel(const float* __restrict__ big0, int n)
{
    __shared__ int has_neg;
    if (threadIdx.x == 0) has_neg = 0;
    __syncthreads();
    for (int i = threadIdx.x; i < n; i += blockDim.x)
        if (big0[i] < 0.0f) has_neg = 1;   // benign race: all writers write 1
    __syncthreads();
    if (threadIdx.x == 0) g_big0_is_logits = has_neg;
}

// One CTA per row. Streaming argmax of:
//   greedy (t==0):  key = logits[v]
//   sampled:        key = logits[v]/t - log(exp_noise[v] + EPS)
// argmax-equivalent to the reference's softmax(l/t) / (noise + EPS)
// (softmax max-shift and normalizer are row constants; log is monotone).
// Output written as FLOAT32 (token id is exactly representable: < 2^24).
__global__ __launch_bounds__(BLOCK) void draft_sampler_kernel(
    const float* __restrict__ big0,
    const float* __restrict__ big1,
    const float* __restrict__ temps,
    float* __restrict__ out,
    int V)
{
    const float* __restrict__ logits = g_big0_is_logits ? big0 : big1;
    const float* __restrict__ noise  = g_big0_is_logits ? big1 : big0;

    const int row = blockIdx.x;
    const float t = temps[row];
    const bool greedy = (t == 0.0f);
    const float inv_t = greedy ? 1.0f : (1.0f / t);

    const float4* __restrict__ l4 =
        reinterpret_cast<const float4*>(logits + (long long)row * V);
    const float4* __restrict__ n4 =
        reinterpret_cast<const float4*>(noise + (long long)row * V);
    const int nvec = V >> 2;  // V = 128000, divisible by 4

    float bestKey = -3.402823466e38f;
    int   bestIdx = 0;

    if (greedy) {
        for (int i = threadIdx.x; i < nvec; i += BLOCK) {
            const float4 lv = l4[i];
            const int base = i << 2;
            if (lv.x > bestKey) { bestKey = lv.x; bestIdx = base;     }
            if (lv.y > bestKey) { bestKey = lv.y; bestIdx = base + 1; }
            if (lv.z > bestKey) { bestKey = lv.z; bestIdx = base + 2; }
            if (lv.w > bestKey) { bestKey = lv.w; bestIdx = base + 3; }
        }
    } else {
        for (int i = threadIdx.x; i < nvec; i += BLOCK) {
            const float4 lv = l4[i];
            const float4 nv = n4[i];
            const float k0 = lv.x * inv_t - __logf(nv.x + EPS);
            const float k1 = lv.y * inv_t - __logf(nv.y + EPS);
            const float k2 = lv.z * inv_t - __logf(nv.z + EPS);
            const float k3 = lv.w * inv_t - __logf(nv.w + EPS);
            const int base = i << 2;
            if (k0 > bestKey) { bestKey = k0; bestIdx = base;     }
            if (k1 > bestKey) { bestKey = k1; bestIdx = base + 1; }
            if (k2 > bestKey) { bestKey = k2; bestIdx = base + 2; }
            if (k3 > bestKey) { bestKey = k3; bestIdx = base + 3; }
        }
    }

    // Warp reduction (tie-break: lower index, matching jnp.argmax first-max)
    #pragma unroll
    for (int off = 16; off > 0; off >>= 1) {
        const float ok = __shfl_down_sync(0xFFFFFFFFu, bestKey, off);
        const int   oi = __shfl_down_sync(0xFFFFFFFFu, bestIdx, off);
        if (ok > bestKey || (ok == bestKey && oi < bestIdx)) {
            bestKey = ok; bestIdx = oi;
        }
    }

    __shared__ float skey[BLOCK / 32];
    __shared__ int   sidx[BLOCK / 32];
    const int wid = threadIdx.x >> 5;
    const int lid = threadIdx.x & 31;
    if (lid == 0) { skey[wid] = bestKey; sidx[wid] = bestIdx; }
    __syncthreads();

    if (wid == 0) {
        constexpr int NW = BLOCK / 32;  // 16
        bestKey = (lid < NW) ? skey[lid] : -3.402823466e38f;
        bestIdx = (lid < NW) ? sidx[lid] : 0x7FFFFFFF;
        #pragma unroll
        for (int off = 8; off > 0; off >>= 1) {
            const float ok = __shfl_down_sync(0xFFFFFFFFu, bestKey, off);
            const int   oi = __shfl_down_sync(0xFFFFFFFFu, bestIdx, off);
            if (ok > bestKey || (ok == bestKey && oi < bestIdx)) {
                bestKey = ok; bestIdx = oi;
            }
        }
        if (lid == 0) out[row] = (float)bestIdx;   // token id < 2^24: exact in fp32
    }
}

extern "C" void kernel_launch(void* const* d_in, const int* in_sizes, int n_in,
                              void* d_out, int out_size)
{
    // Identify inputs by SIZE, not by assumed order:
    //   temperatures -> the (unique) smallest input [B]
    //   logits / exp_noise -> the two big inputs [B*V] (disambiguated on-device)
    int smallIdx = 0;
    for (int i = 1; i < n_in; i++)
        if (in_sizes[i] < in_sizes[smallIdx]) smallIdx = i;

    int bigIdx0 = -1, bigIdx1 = -1;
    for (int i = 0; i < n_in; i++) {
        if (i == smallIdx) continue;
        if (bigIdx0 < 0) bigIdx0 = i; else bigIdx1 = i;
    }

    const float* temps = (const float*)d_in[smallIdx];
    const float* big0  = (const float*)d_in[bigIdx0];
    const float* big1  = (const float*)d_in[bigIdx1];
    float* out = (float*)d_out;                 // __output__ is float32

    const int B = in_sizes[smallIdx];           // 256
    const int V = in_sizes[bigIdx0] / B;        // 128000

    // Resolve which big tensor is logits (contains negatives) on-device.
    detect_kernel<<<1, 256>>>(big0, V < 4096 ? V : 4096);
    draft_sampler_kernel<<<B, BLOCK>>>(big0, big1, temps, out, V);
}